// round 1
// baseline (speedup 1.0000x reference)
#include <cuda_runtime.h>
#include <math.h>

#define N_G    4096
#define BATCH  2
#define H_IMG  128
#define W_IMG  128
#define NSPLIT 8
#define TY     8
#define CHUNK  64
#define NPB    (N_G / NSPLIT)   // 512 gaussians per split
#define NYT    (H_IMG / TY)     // 16 y-tiles

// Scratch (device globals; no allocation allowed)
__device__ float  g_Ex[BATCH * N_G * W_IMG];          // 4 MB
__device__ float  g_Ey[BATCH * N_G * H_IMG];          // 4 MB
__device__ float4 g_G[N_G];                           // 64 KB: (op*r, op*g, op*b, op)
__device__ float4 g_part[NSPLIT * BATCH * H_IMG * W_IMG];  // 4 MB partial sums

// ---------------------------------------------------------------------------
// Kernel 1: per (b, n) compute projection and fill Ex/Ey rows; fill G.
// grid = BATCH * N_G blocks, 128 threads (thread = pixel coordinate).
// ---------------------------------------------------------------------------
__global__ __launch_bounds__(128) void prep_kernel(
    const float* __restrict__ pos,   // [N,3]
    const float* __restrict__ col,   // [N,3]
    const float* __restrict__ opa,   // [N,1]
    const float* __restrict__ sca,   // [N,1]
    const float* __restrict__ qv,    // [B,4]
    const float* __restrict__ tv)    // [B,3]
{
    int bn = blockIdx.x;
    int b  = bn / N_G;
    int n  = bn - b * N_G;
    int x  = threadIdx.x;

    // quaternion -> rotation (normalized)
    float qw = qv[b*4+0], qx = qv[b*4+1], qy = qv[b*4+2], qz = qv[b*4+3];
    float inv = 1.0f / sqrtf(qw*qw + qx*qx + qy*qy + qz*qz);
    qw *= inv; qx *= inv; qy *= inv; qz *= inv;

    float r00 = 1.f - 2.f*(qy*qy + qz*qz);
    float r01 = 2.f*(qx*qy - qz*qw);
    float r02 = 2.f*(qx*qz + qy*qw);
    float r10 = 2.f*(qx*qy + qz*qw);
    float r11 = 1.f - 2.f*(qx*qx + qz*qz);
    float r12 = 2.f*(qy*qz - qx*qw);
    float r20 = 2.f*(qx*qz - qy*qw);
    float r21 = 2.f*(qy*qz + qx*qw);
    float r22 = 1.f - 2.f*(qx*qx + qy*qy);

    float p0 = pos[n*3+0], p1 = pos[n*3+1], p2 = pos[n*3+2];
    float cx = r00*p0 + r01*p1 + r02*p2 + tv[b*3+0];
    float cy = r10*p0 + r11*p1 + r12*p2 + tv[b*3+1];
    float cz = r20*p0 + r21*p1 + r22*p2 + tv[b*3+2];

    float invz = 1.0f / cz;
    float px = cx * invz * 500.0f + 64.0f;   // FX, CX
    float py = cy * invz * 500.0f + 64.0f;   // FY, CY

    float s      = sca[n];
    float inv2v  = 0.5f / (s * s);

    float fx = (float)x;
    float dx = fx - px;
    float dy = fx - py;   // same thread index reused as y coordinate (H == W)

    g_Ex[(b*N_G + n)*W_IMG + x] = expf(-dx*dx*inv2v);
    g_Ey[(b*N_G + n)*H_IMG + x] = expf(-dy*dy*inv2v);

    if (b == 0 && x == 0) {
        float o = opa[n];
        g_G[n] = make_float4(o*col[n*3+0], o*col[n*3+1], o*col[n*3+2], o);
    }
}

// ---------------------------------------------------------------------------
// Kernel 2: main contraction. Block = (batch, y-tile of 8 rows, n-split).
// 128 threads, thread t owns column x=t across TY rows -> 8 float4 accumulators.
// ---------------------------------------------------------------------------
__global__ __launch_bounds__(128) void splat_kernel()
{
    int blk = blockIdx.x;
    int ns  = blk % NSPLIT;
    int yt  = (blk / NSPLIT) % NYT;
    int b   = blk / (NSPLIT * NYT);
    int x   = threadIdx.x;
    int y0  = yt * TY;
    int n0  = ns * NPB;

    __shared__ float  sEx[CHUNK * W_IMG];     // 32 KB
    __shared__ float4 sEy[CHUNK * 2];         // 2 KB : 8 ey values per gaussian
    __shared__ float4 sG [CHUNK];             // 1 KB

    float4 acc[TY];
#pragma unroll
    for (int j = 0; j < TY; j++) acc[j] = make_float4(0.f, 0.f, 0.f, 0.f);

    const float* Exb = g_Ex + (size_t)(b*N_G + n0) * W_IMG;
    const float* Eyb = g_Ey + (size_t)(b*N_G + n0) * H_IMG + y0;

    for (int c0 = 0; c0 < NPB; c0 += CHUNK) {
        __syncthreads();
        // Ex chunk: CHUNK*W contiguous floats -> float4 copy
        {
            const float4* src = (const float4*)(Exb + c0 * W_IMG);
            float4* dst = (float4*)sEx;
#pragma unroll
            for (int i = 0; i < (CHUNK * W_IMG / 4) / 128; i++)
                dst[i*128 + x] = src[i*128 + x];
        }
        // Ey chunk: CHUNK rows x TY cols (stride H). 128 float4 = 1 per thread.
        {
            int nl   = x >> 1;
            int half = x & 1;
            sEy[x] = *(const float4*)(Eyb + (c0 + nl) * H_IMG + half * 4);
        }
        // G chunk: CHUNK float4
        if (x < CHUNK) sG[x] = g_G[n0 + c0 + x];
        __syncthreads();

#pragma unroll 4
        for (int nl = 0; nl < CHUNK; nl++) {
            float  ex = sEx[nl * W_IMG + x];
            float4 g  = sG[nl];
            float4 eA = sEy[nl*2 + 0];
            float4 eB = sEy[nl*2 + 1];
            float eyv[TY];
            eyv[0] = eA.x; eyv[1] = eA.y; eyv[2] = eA.z; eyv[3] = eA.w;
            eyv[4] = eB.x; eyv[5] = eB.y; eyv[6] = eB.z; eyv[7] = eB.w;
#pragma unroll
            for (int j = 0; j < TY; j++) {
                float w = ex * eyv[j];
                acc[j].x += w * g.x;
                acc[j].y += w * g.y;
                acc[j].z += w * g.z;
                acc[j].w += w * g.w;
            }
        }
    }

    float4* pp = g_part + (size_t)(ns*BATCH + b) * H_IMG * W_IMG;
#pragma unroll
    for (int j = 0; j < TY; j++)
        pp[(y0 + j) * W_IMG + x] = acc[j];
}

// ---------------------------------------------------------------------------
// Kernel 3: reduce n-splits, normalize, write [B,3,H,W]
// ---------------------------------------------------------------------------
__global__ __launch_bounds__(256) void finalize_kernel(float* __restrict__ out)
{
    int idx = blockIdx.x * blockDim.x + threadIdx.x;
    if (idx >= BATCH * H_IMG * W_IMG) return;
    int b = idx / (H_IMG * W_IMG);
    int p = idx - b * (H_IMG * W_IMG);

    float sx = 0.f, sy = 0.f, sz = 0.f, sw = 0.f;
#pragma unroll
    for (int ns = 0; ns < NSPLIT; ns++) {
        float4 v = g_part[(size_t)(ns*BATCH + b) * H_IMG * W_IMG + p];
        sx += v.x; sy += v.y; sz += v.z; sw += v.w;
    }
    float invd = 1.0f / (sw + 1e-8f);
    size_t base = (size_t)b * 3 * H_IMG * W_IMG;
    out[base + 0*H_IMG*W_IMG + p] = sx * invd;
    out[base + 1*H_IMG*W_IMG + p] = sy * invd;
    out[base + 2*H_IMG*W_IMG + p] = sz * invd;
}

// ---------------------------------------------------------------------------
extern "C" void kernel_launch(void* const* d_in, const int* in_sizes, int n_in,
                              void* d_out, int out_size)
{
    const float* positions = (const float*)d_in[0];
    const float* colors    = (const float*)d_in[1];
    const float* opacities = (const float*)d_in[2];
    const float* scales    = (const float*)d_in[3];
    const float* qvec      = (const float*)d_in[4];
    const float* tvec      = (const float*)d_in[5];
    float* out = (float*)d_out;

    prep_kernel<<<BATCH * N_G, 128>>>(positions, colors, opacities, scales, qvec, tvec);
    splat_kernel<<<BATCH * NYT * NSPLIT, 128>>>();
    finalize_kernel<<<(BATCH * H_IMG * W_IMG + 255) / 256, 256>>>(out);
}